// round 10
// baseline (speedup 1.0000x reference)
#include <cuda_runtime.h>
#include <math.h>

// GAT layer. N=4096, F_IN=128, F_OUT=64, H=4.
// Output: concat( out[4096,256], mask_ln[4096,4096] ) fp32.

#define NEG_INF -1e9f

// ---- scratch (device globals; no allocation allowed) ----
__device__ __align__(16) float g_mask[16777216];   // [4096][4096]
__device__ __align__(16) float g_proj[1048576];    // [n][256] (c = h*64+o)
__device__ __align__(16) float g_skip[1048576];    // [n][256]
__device__ float g_ss[16384];        // [h][n]
__device__ float g_st[16384];        // [h][n]
__device__ float g_pm[131072];       // [h][8 stripes][4096] partial col max
__device__ float g_pz[131072];       // partial col sum
__device__ float g_m[16384];         // [h][j] col max
__device__ float g_iz[16384];        // [h][j] 1/Z

// ---- packed f32x2 helpers ----
__device__ __forceinline__ unsigned long long pk2(float x, float y) {
    unsigned long long r;
    asm("mov.b64 %0, {%1,%2};" : "=l"(r) : "f"(x), "f"(y));
    return r;
}
__device__ __forceinline__ void upk2(unsigned long long v, float& x, float& y) {
    asm("mov.b64 {%0,%1}, %2;" : "=f"(x), "=f"(y) : "l"(v));
}
__device__ __forceinline__ unsigned long long fma2_(unsigned long long a,
                                                    unsigned long long b,
                                                    unsigned long long c) {
    unsigned long long d;
    asm("fma.rn.f32x2 %0, %1, %2, %3;" : "=l"(d) : "l"(a), "l"(b), "l"(c));
    return d;
}

__device__ __forceinline__ float bred256(float v, float* red, int tid) {
    red[tid] = v;
    __syncthreads();
#pragma unroll
    for (int s = 128; s > 0; s >>= 1) {
        if (tid < s) red[tid] += red[tid + s];
        __syncthreads();
    }
    float r = red[0];
    __syncthreads();
    return r;
}

// =====================================================================
// K1: projection GEMM  g_proj[n][h*64+o] = nodes @ pp[h].  grid (64,4).
// B staged transposed so global loads stay coalesced.
// =====================================================================
__global__ void __launch_bounds__(256) k_projg(
    const float* __restrict__ nodes, const float* __restrict__ pp) {
    __shared__ float x_s[64][129];
    __shared__ float w_s[128][65];
    int tid = threadIdx.x;
    int n0 = blockIdx.x * 64, h = blockIdx.y;
#pragma unroll
    for (int it = 0; it < 32; it++) {
        int idx = it * 256 + tid;          // 8192
        int r = idx >> 7, f = idx & 127;
        x_s[r][f] = nodes[(n0 + r) * 128 + f];
        int ff = idx >> 6, o = idx & 63;
        w_s[ff][o] = pp[(h * 128 + ff) * 64 + o];
    }
    __syncthreads();
    int ti = tid >> 4, tc = tid & 15;
    float acc[4][4];
#pragma unroll
    for (int i = 0; i < 4; i++)
#pragma unroll
        for (int j = 0; j < 4; j++) acc[i][j] = 0.f;
#pragma unroll 4
    for (int k = 0; k < 128; k++) {
        float a0 = x_s[ti * 4 + 0][k], a1 = x_s[ti * 4 + 1][k];
        float a2 = x_s[ti * 4 + 2][k], a3 = x_s[ti * 4 + 3][k];
        float b0 = w_s[k][tc * 4 + 0], b1 = w_s[k][tc * 4 + 1];
        float b2 = w_s[k][tc * 4 + 2], b3 = w_s[k][tc * 4 + 3];
        acc[0][0] = fmaf(a0, b0, acc[0][0]); acc[0][1] = fmaf(a0, b1, acc[0][1]);
        acc[0][2] = fmaf(a0, b2, acc[0][2]); acc[0][3] = fmaf(a0, b3, acc[0][3]);
        acc[1][0] = fmaf(a1, b0, acc[1][0]); acc[1][1] = fmaf(a1, b1, acc[1][1]);
        acc[1][2] = fmaf(a1, b2, acc[1][2]); acc[1][3] = fmaf(a1, b3, acc[1][3]);
        acc[2][0] = fmaf(a2, b0, acc[2][0]); acc[2][1] = fmaf(a2, b1, acc[2][1]);
        acc[2][2] = fmaf(a2, b2, acc[2][2]); acc[2][3] = fmaf(a2, b3, acc[2][3]);
        acc[3][0] = fmaf(a3, b0, acc[3][0]); acc[3][1] = fmaf(a3, b1, acc[3][1]);
        acc[3][2] = fmaf(a3, b2, acc[3][2]); acc[3][3] = fmaf(a3, b3, acc[3][3]);
    }
#pragma unroll
    for (int i = 0; i < 4; i++)
#pragma unroll
        for (int j = 0; j < 4; j++)
            g_proj[(n0 + ti * 4 + i) * 256 + h * 64 + tc * 4 + j] = acc[i][j];
}

// =====================================================================
// K1b: skip GEMM g_skip = nodes @ skw^T. grid (64,4).
// =====================================================================
__global__ void __launch_bounds__(256) k_skip(
    const float* __restrict__ nodes, const float* __restrict__ skw) {
    __shared__ float x_s[64][129];
    __shared__ float w_s[64][129];
    int tid = threadIdx.x;
    int n0 = blockIdx.x * 64, c0 = blockIdx.y * 64;
#pragma unroll
    for (int it = 0; it < 32; it++) {
        int idx = it * 256 + tid;
        int r = idx >> 7, f = idx & 127;
        x_s[r][f] = nodes[(n0 + r) * 128 + f];
        w_s[r][f] = skw[(c0 + r) * 128 + f];
    }
    __syncthreads();
    int ti = tid >> 4, tc = tid & 15;
    float acc[4][4];
#pragma unroll
    for (int i = 0; i < 4; i++)
#pragma unroll
        for (int j = 0; j < 4; j++) acc[i][j] = 0.f;
#pragma unroll 4
    for (int k = 0; k < 128; k++) {
        float a0 = x_s[ti * 4 + 0][k], a1 = x_s[ti * 4 + 1][k];
        float a2 = x_s[ti * 4 + 2][k], a3 = x_s[ti * 4 + 3][k];
        float b0 = w_s[tc * 4 + 0][k], b1 = w_s[tc * 4 + 1][k];
        float b2 = w_s[tc * 4 + 2][k], b3 = w_s[tc * 4 + 3][k];
        acc[0][0] = fmaf(a0, b0, acc[0][0]); acc[0][1] = fmaf(a0, b1, acc[0][1]);
        acc[0][2] = fmaf(a0, b2, acc[0][2]); acc[0][3] = fmaf(a0, b3, acc[0][3]);
        acc[1][0] = fmaf(a1, b0, acc[1][0]); acc[1][1] = fmaf(a1, b1, acc[1][1]);
        acc[1][2] = fmaf(a1, b2, acc[1][2]); acc[1][3] = fmaf(a1, b3, acc[1][3]);
        acc[2][0] = fmaf(a2, b0, acc[2][0]); acc[2][1] = fmaf(a2, b1, acc[2][1]);
        acc[2][2] = fmaf(a2, b2, acc[2][2]); acc[2][3] = fmaf(a2, b3, acc[2][3]);
        acc[3][0] = fmaf(a3, b0, acc[3][0]); acc[3][1] = fmaf(a3, b1, acc[3][1]);
        acc[3][2] = fmaf(a3, b2, acc[3][2]); acc[3][3] = fmaf(a3, b3, acc[3][3]);
    }
#pragma unroll
    for (int i = 0; i < 4; i++)
#pragma unroll
        for (int j = 0; j < 4; j++)
            g_skip[(n0 + ti * 4 + i) * 256 + c0 + tc * 4 + j] = acc[i][j];
}

// =====================================================================
// K1c: scalar scores via warp dot. grid 2048, 256 threads (8 warps).
// =====================================================================
__global__ void __launch_bounds__(256) k_score(
    const float* __restrict__ scs, const float* __restrict__ sct) {
    int w = threadIdx.x >> 5, l = threadIdx.x & 31;
    int hn = blockIdx.x * 8 + w;       // 0..16383
    int h = hn >> 12, n = hn & 4095;
    float p0 = g_proj[n * 256 + h * 64 + l];
    float p1 = g_proj[n * 256 + h * 64 + 32 + l];
    float vs = p0 * scs[h * 64 + l] + p1 * scs[h * 64 + 32 + l];
    float vt = p0 * sct[h * 64 + l] + p1 * sct[h * 64 + 32 + l];
#pragma unroll
    for (int s = 16; s > 0; s >>= 1) {
        vs += __shfl_xor_sync(0xffffffffu, vs, s);
        vt += __shfl_xor_sync(0xffffffffu, vt, s);
    }
    if (l == 0) {
        g_ss[h * 4096 + n] = vs;
        g_st[h * 4096 + n] = vt;
    }
}

// =====================================================================
// K2: mask build + per-row LayerNorm, float4. grid 4096, 256 threads.
// =====================================================================
__global__ void __launch_bounds__(256) k_mask(
    const float4* __restrict__ deg4, const float4* __restrict__ bond4,
    const int* __restrict__ cutp, float4* __restrict__ out_ln4) {
    __shared__ float red[256];
    int i = blockIdx.x, tid = threadIdx.x;
    float cut = (float)cutp[0];
    float4* gm4 = reinterpret_cast<float4*>(g_mask);
    float4 mv[4];
    float ssum = 0.f;
#pragma unroll
    for (int k = 0; k < 4; k++) {
        int idx = i * 1024 + tid + k * 256;
        float4 d = deg4[idx], b = bond4[idx];
        float4 m;
        {
            float w0 = d.x + b.x; m.x = (w0 > 0.f) ? w0 : ((b.x > cut) ? (b.x + w0) : NEG_INF);
            float w1 = d.y + b.y; m.y = (w1 > 0.f) ? w1 : ((b.y > cut) ? (b.y + w1) : NEG_INF);
            float w2 = d.z + b.z; m.z = (w2 > 0.f) ? w2 : ((b.z > cut) ? (b.z + w2) : NEG_INF);
            float w3 = d.w + b.w; m.w = (w3 > 0.f) ? w3 : ((b.w > cut) ? (b.w + w3) : NEG_INF);
        }
        mv[k] = m;
        gm4[idx] = m;
        ssum += m.x + m.y + m.z + m.w;
    }
    float mu = bred256(ssum, red, tid) * (1.f / 4096.f);
    float s2 = 0.f;
#pragma unroll
    for (int k = 0; k < 4; k++) {
        float dx = mv[k].x - mu, dy = mv[k].y - mu, dz = mv[k].z - mu, dw = mv[k].w - mu;
        s2 = fmaf(dx, dx, s2); s2 = fmaf(dy, dy, s2);
        s2 = fmaf(dz, dz, s2); s2 = fmaf(dw, dw, s2);
    }
    float var = bred256(s2, red, tid) * (1.f / 4096.f);
    float rstd = rsqrtf(var + 1e-5f);
#pragma unroll
    for (int k = 0; k < 4; k++) {
        int idx = i * 1024 + tid + k * 256;
        float4 o;
        o.x = (mv[k].x - mu) * rstd; o.y = (mv[k].y - mu) * rstd;
        o.z = (mv[k].z - mu) * rstd; o.w = (mv[k].w - mu) * rstd;
        out_ln4[idx] = o;
    }
}

// =====================================================================
// K3: partial column softmax stats, 8-elem chunks (MLP + one exp/elem).
// grid (32,8,4), 128 threads.
// =====================================================================
__global__ void __launch_bounds__(128) k_stats() {
    __shared__ float ss_s[512];
    int tid = threadIdx.x;
    int jc = blockIdx.x, istr = blockIdx.y, h = blockIdx.z;
    int j = jc * 128 + tid;
    int i0 = istr * 512;
#pragma unroll
    for (int k = 0; k < 4; k++) ss_s[tid + k * 128] = g_ss[h * 4096 + i0 + tid + k * 128];
    __syncthreads();
    float stj = g_st[h * 4096 + j];
    float m = -INFINITY, z = 0.f;
    for (int c = 0; c < 512; c += 8) {
        float mkv[8];
#pragma unroll
        for (int k = 0; k < 8; k++)
            mkv[k] = g_mask[(unsigned)(i0 + c + k) * 4096u + (unsigned)j];
        float e[8];
#pragma unroll
        for (int k = 0; k < 8; k++) {
            float t = ss_s[c + k] + stj;
            t = fmaxf(t, 0.2f * t);
            e[k] = t + mkv[k];
        }
        float cm = fmaxf(fmaxf(fmaxf(e[0], e[1]), fmaxf(e[2], e[3])),
                         fmaxf(fmaxf(e[4], e[5]), fmaxf(e[6], e[7])));
        float nm = fmaxf(m, cm);
        float cz = 0.f;
#pragma unroll
        for (int k = 0; k < 8; k++) cz += __expf(e[k] - nm);
        z = fmaf(z, __expf(m - nm), cz);
        m = nm;
    }
    g_pm[(h * 8 + istr) * 4096 + j] = m;
    g_pz[(h * 8 + istr) * 4096 + j] = z;
}

// =====================================================================
// K4: combine stripe partials. grid 64, 256 threads.
// =====================================================================
__global__ void __launch_bounds__(256) k_comb() {
    int idx = blockIdx.x * 256 + threadIdx.x;
    int h = idx >> 12, j = idx & 4095;
    float m = -INFINITY;
#pragma unroll
    for (int s = 0; s < 8; s++) m = fmaxf(m, g_pm[(h * 8 + s) * 4096 + j]);
    float z = 0.f;
#pragma unroll
    for (int s = 0; s < 8; s++)
        z += g_pz[(h * 8 + s) * 4096 + j] * __expf(g_pm[(h * 8 + s) * 4096 + j] - m);
    g_m[h * 4096 + j] = m;
    g_iz[h * 4096 + j] = 1.0f / z;
}

// =====================================================================
// K5: aggregation + skip + ELU, double-buffered. grid (32,4), 256 thr.
// Thread tile 8 rows x 8 f; per 32-j tile: prefetch (LDG->regs) for t+1,
// FMA on buffer t, then w-compute + STS into buffer t+1, single sync.
// =====================================================================
__global__ void __launch_bounds__(256) k_agg(float* __restrict__ out) {
    __shared__ __align__(16) float w_s[2][128][33];
    __shared__ __align__(16) float proj_s[2][32][68];
    __shared__ float ss_s[128];

    int tid = threadIdx.x;
    int h = blockIdx.y;
    int i0 = blockIdx.x * 128;
    if (tid < 128) ss_s[tid] = g_ss[h * 4096 + i0 + tid];

    int jhalf = tid >> 7;
    int ct = tid & 127;
    int i_g = ct >> 3;
    int f_g = ct & 7;
    int jw = tid & 31;
    int iw = tid >> 5;
    int jlo = jhalf * 16;

    unsigned long long acc[8][4];
#pragma unroll
    for (int r = 0; r < 8; r++)
#pragma unroll
        for (int q = 0; q < 4; q++) acc[r][q] = 0ull;

    __syncthreads();  // ss_s ready

    // ---- prologue: fill buffer 0 for tile j0 = 0 ----
    {
        float stj = g_st[h * 4096 + jw];
        float mj = g_m[h * 4096 + jw];
        float izj = g_iz[h * 4096 + jw];
        float pv[8];
#pragma unroll
        for (int p = 0; p < 8; p++) {
            int idx = p * 256 + tid;
            pv[p] = g_proj[(idx >> 6) * 256 + h * 64 + (idx & 63)];
        }
#pragma unroll
        for (int p = 0; p < 16; p++) {
            int il = p * 8 + iw;
            float e = ss_s[il] + stj;
            e = fmaxf(e, 0.2f * e);
            e += g_mask[(unsigned)(i0 + il) * 4096u + (unsigned)jw];
            w_s[0][il][jw] = __expf(e - mj) * izj;
        }
#pragma unroll
        for (int p = 0; p < 8; p++) {
            int idx = p * 256 + tid;
            proj_s[0][idx >> 6][idx & 63] = pv[p];
        }
    }
    __syncthreads();

    for (int t = 0; t < 128; t++) {
        int cur = t & 1, nxt = cur ^ 1;
        int nj0 = (t + 1) * 32;
        bool pf = (t + 1) < 128;

        float stj = 0.f, mj = 0.f, izj = 1.f;
        float mk[16], pv[8];
        if (pf) {
            stj = g_st[h * 4096 + nj0 + jw];
            mj = g_m[h * 4096 + nj0 + jw];
            izj = g_iz[h * 4096 + nj0 + jw];
#pragma unroll
            for (int p = 0; p < 8; p++) {
                int idx = p * 256 + tid;
                pv[p] = g_proj[(nj0 + (idx >> 6)) * 256 + h * 64 + (idx & 63)];
            }
#pragma unroll
            for (int p = 0; p < 16; p++) {
                int il = p * 8 + iw;
                mk[p] = g_mask[(unsigned)(i0 + il) * 4096u + (unsigned)(nj0 + jw)];
            }
        }

        // ---- FMA on current buffer ----
#pragma unroll
        for (int jj = 0; jj < 16; jj++) {
            int jl = jlo + jj;
            ulonglong2 pA = *(const ulonglong2*)&proj_s[cur][jl][f_g * 4];
            ulonglong2 pB = *(const ulonglong2*)&proj_s[cur][jl][32 + f_g * 4];
            float w0 = w_s[cur][i_g * 4 + 0][jl];
            float w1 = w_s[cur][i_g * 4 + 1][jl];
            float w2 = w_s[cur][i_g * 4 + 2][jl];
            float w3 = w_s[cur][i_g * 4 + 3][jl];
            float w4 = w_s[cur][64 + i_g * 4 + 0][jl];
            float w5 = w_s[cur][64 + i_g * 4 + 1][jl];
            float w6 = w_s[cur][64 + i_g * 4 + 2][jl];
            float w7 = w_s[cur][64 + i_g * 4 + 3][jl];
            unsigned long long u0 = pk2(w0, w0), u1 = pk2(w1, w1);
            unsigned long long u2 = pk2(w2, w2), u3 = pk2(w3, w3);
            unsigned long long u4 = pk2(w4, w4), u5 = pk2(w5, w5);
            unsigned long long u6 = pk2(w6, w6), u7 = pk2(w7, w7);
            acc[0][0] = fma2_(u0, pA.x, acc[0][0]); acc[0][1] = fma2_(u0, pA.y, acc[0][1]);
            acc[0][2] = fma2_(u0, pB.x, acc[0][2]); acc[0][3] = fma2_(u0, pB.y, acc[0][3]);
            acc[1][0] = fma2_(u1, pA.x, acc[1][0]); acc[1][1] = fma2_(u1, pA.y, acc[1][1]);
            acc[1][2] = fma2_(u1, pB.x, acc[1][2]); acc[1][3] = fma2_(u1, pB.y, acc[1][3]);
            acc[2][0] = fma2_(u2, pA.x, acc[2][0]); acc[2][1] = fma2_(u2, pA.y, acc[2][1]);
            acc[2][2] = fma2_(u2, pB.x, acc[2][2]); acc[2][3] = fma2_(u2, pB.y, acc[2][3]);
            acc[3][0] = fma2_(u3, pA.x, acc[3][0]); acc[3][1] = fma2_(u3, pA.y, acc[3][1]);
            acc[3][2] = fma2_(u3, pB.x, acc[3][2]); acc[3][3] = fma2_(u3, pB.y, acc[3][3]);
            acc[4][0] = fma2_(u4, pA.x, acc[4][0]); acc[4][1] = fma2_(u4, pA.y, acc[4][1]);
            acc[4][2] = fma2_(u4, pB.x, acc[4][2]); acc[4][3] = fma2_(u4, pB.y, acc[4][3]);
            acc[5][0] = fma2_(u5, pA.x, acc[5][0]); acc[5][1] = fma2_(u5, pA.y, acc[5][1]);
            acc[5][2] = fma2_(u5, pB.x, acc[5][2]); acc[5][3] = fma2_(u5, pB.y, acc[5][3]);
            acc[6][0] = fma2_(u6, pA.x, acc[6][0]); acc[6][1] = fma2_(u6, pA.y, acc[6][1]);
            acc[6][2] = fma2_(u6, pB.x, acc[6][2]); acc[6][3] = fma2_(u6, pB.y, acc[6][3]);
            acc[7][0] = fma2_(u7, pA.x, acc[7][0]); acc[7][1] = fma2_(u7, pA.y, acc[7][1]);
            acc[7][2] = fma2_(u7, pB.x, acc[7][2]); acc[7][3] = fma2_(u7, pB.y, acc[7][3]);
        }

        // ---- write next buffer ----
        if (pf) {
#pragma unroll
            for (int p = 0; p < 16; p++) {
                int il = p * 8 + iw;
                float e = ss_s[il] + stj;
                e = fmaxf(e, 0.2f * e);
                e += mk[p];
                w_s[nxt][il][jw] = __expf(e - mj) * izj;
            }
#pragma unroll
            for (int p = 0; p < 8; p++) {
                int idx = p * 256 + tid;
                proj_s[nxt][idx >> 6][idx & 63] = pv[p];
            }
        }
        __syncthreads();
    }

    // ---- pair-reduce the two j-halves through smem, skip+ELU epilogue ----
    unsigned long long* red = reinterpret_cast<unsigned long long*>(&w_s[0][0][0]);

    if (jhalf == 1) {
#pragma unroll
        for (int r = 0; r < 4; r++)
#pragma unroll
            for (int q = 0; q < 4; q++) red[ct * 16 + r * 4 + q] = acc[r][q];
    }
    __syncthreads();
    if (jhalf == 0) {
#pragma unroll
        for (int r = 0; r < 4; r++) {
            int n = i0 + i_g * 4 + r;
#pragma unroll
            for (int q = 0; q < 4; q++) {
                float x0, x1, y0, y1;
                upk2(acc[r][q], x0, x1);
                upk2(red[ct * 16 + r * 4 + q], y0, y1);
                x0 += y0; x1 += y1;
                int cb = (q < 2) ? (f_g * 4 + q * 2) : (32 + f_g * 4 + (q - 2) * 2);
                int c = h * 64 + cb;
                float v0 = x0 + g_skip[n * 256 + c];
                float v1 = x1 + g_skip[n * 256 + c + 1];
                out[n * 256 + c] = (v0 > 0.f) ? v0 : expm1f(v0);
                out[n * 256 + c + 1] = (v1 > 0.f) ? v1 : expm1f(v1);
            }
        }
    }
    __syncthreads();
    if (jhalf == 0) {
#pragma unroll
        for (int r = 0; r < 4; r++)
#pragma unroll
            for (int q = 0; q < 4; q++) red[ct * 16 + r * 4 + q] = acc[4 + r][q];
    }
    __syncthreads();
    if (jhalf == 1) {
#pragma unroll
        for (int r = 0; r < 4; r++) {
            int n = i0 + 64 + i_g * 4 + r;
#pragma unroll
            for (int q = 0; q < 4; q++) {
                float x0, x1, y0, y1;
                upk2(acc[4 + r][q], x0, x1);
                upk2(red[ct * 16 + r * 4 + q], y0, y1);
                x0 += y0; x1 += y1;
                int cb = (q < 2) ? (f_g * 4 + q * 2) : (32 + f_g * 4 + (q - 2) * 2);
                int c = h * 64 + cb;
                float v0 = x0 + g_skip[n * 256 + c];
                float v1 = x1 + g_skip[n * 256 + c + 1];
                out[n * 256 + c] = (v0 > 0.f) ? v0 : expm1f(v0);
                out[n * 256 + c + 1] = (v1 > 0.f) ? v1 : expm1f(v1);
            }
        }
    }
}

// =====================================================================
extern "C" void kernel_launch(void* const* d_in, const int* in_sizes, int n_in,
                              void* d_out, int out_size) {
    const float* nodes = (const float*)d_in[0];
    const float* deg = (const float*)d_in[1];
    const float* bond = (const float*)d_in[3];
    const float* pp = (const float*)d_in[4];
    const float* scs = (const float*)d_in[5];
    const float* sct = (const float*)d_in[6];
    const float* skw = (const float*)d_in[7];
    const int* cutp = (const int*)d_in[8];

    float* out0 = (float*)d_out;        // [4096,256]
    float* out_ln = out0 + 4096 * 256;  // [4096,4096]

    k_projg<<<dim3(64, 4), 256>>>(nodes, pp);
    k_skip<<<dim3(64, 4), 256>>>(nodes, skw);
    k_score<<<2048, 256>>>(scs, sct);
    k_mask<<<4096, 256>>>((const float4*)deg, (const float4*)bond, cutp,
                          (float4*)out_ln);
    k_stats<<<dim3(32, 8, 4), 128>>>();
    k_comb<<<64, 256>>>();
    k_agg<<<dim3(32, 4), 256>>>(out0);
}

// round 14
// speedup vs baseline: 1.8346x; 1.8346x over previous
#include <cuda_runtime.h>
#include <math.h>

// GAT layer. N=4096, F_IN=128, F_OUT=64, H=4.
// Output: concat( out[4096,256], mask_ln[4096,4096] ) fp32.

#define NEG_INF -1e9f

// ---- scratch (device globals; no allocation allowed) ----
__device__ __align__(16) float g_mask[16777216];   // [4096][4096]
__device__ __align__(16) float g_proj[1048576];    // [n][256] (c = h*64+o)
__device__ __align__(16) float g_skip[1048576];    // [n][256]
__device__ float g_ss[16384];        // [h][n]
__device__ float g_st[16384];        // [h][n]
__device__ float g_pm[131072];       // [h][8 stripes][4096] partial col max
__device__ float g_pz[131072];       // partial col sum
__device__ float g_m[16384];         // [h][j] col max
__device__ float g_iz[16384];        // [h][j] 1/Z

// ---- packed f32x2 helpers ----
__device__ __forceinline__ unsigned long long pk2(float x, float y) {
    unsigned long long r;
    asm("mov.b64 %0, {%1,%2};" : "=l"(r) : "f"(x), "f"(y));
    return r;
}
__device__ __forceinline__ void upk2(unsigned long long v, float& x, float& y) {
    asm("mov.b64 {%0,%1}, %2;" : "=f"(x), "=f"(y) : "l"(v));
}
__device__ __forceinline__ unsigned long long fma2_(unsigned long long a,
                                                    unsigned long long b,
                                                    unsigned long long c) {
    unsigned long long d;
    asm("fma.rn.f32x2 %0, %1, %2, %3;" : "=l"(d) : "l"(a), "l"(b), "l"(c));
    return d;
}

__device__ __forceinline__ float bred256(float v, float* red, int tid) {
    red[tid] = v;
    __syncthreads();
#pragma unroll
    for (int s = 128; s > 0; s >>= 1) {
        if (tid < s) red[tid] += red[tid + s];
        __syncthreads();
    }
    float r = red[0];
    __syncthreads();
    return r;
}

// =====================================================================
// K1: projection GEMM  g_proj[n][h*64+o] = nodes @ pp[h].  grid (64,4).
// =====================================================================
__global__ void __launch_bounds__(256) k_projg(
    const float* __restrict__ nodes, const float* __restrict__ pp) {
    __shared__ float x_s[64][129];
    __shared__ float w_s[128][65];
    int tid = threadIdx.x;
    int n0 = blockIdx.x * 64, h = blockIdx.y;
#pragma unroll
    for (int it = 0; it < 32; it++) {
        int idx = it * 256 + tid;
        int r = idx >> 7, f = idx & 127;
        x_s[r][f] = nodes[(n0 + r) * 128 + f];
        int ff = idx >> 6, o = idx & 63;
        w_s[ff][o] = pp[(h * 128 + ff) * 64 + o];
    }
    __syncthreads();
    int ti = tid >> 4, tc = tid & 15;
    float acc[4][4];
#pragma unroll
    for (int i = 0; i < 4; i++)
#pragma unroll
        for (int j = 0; j < 4; j++) acc[i][j] = 0.f;
#pragma unroll 4
    for (int k = 0; k < 128; k++) {
        float a0 = x_s[ti * 4 + 0][k], a1 = x_s[ti * 4 + 1][k];
        float a2 = x_s[ti * 4 + 2][k], a3 = x_s[ti * 4 + 3][k];
        float b0 = w_s[k][tc * 4 + 0], b1 = w_s[k][tc * 4 + 1];
        float b2 = w_s[k][tc * 4 + 2], b3 = w_s[k][tc * 4 + 3];
        acc[0][0] = fmaf(a0, b0, acc[0][0]); acc[0][1] = fmaf(a0, b1, acc[0][1]);
        acc[0][2] = fmaf(a0, b2, acc[0][2]); acc[0][3] = fmaf(a0, b3, acc[0][3]);
        acc[1][0] = fmaf(a1, b0, acc[1][0]); acc[1][1] = fmaf(a1, b1, acc[1][1]);
        acc[1][2] = fmaf(a1, b2, acc[1][2]); acc[1][3] = fmaf(a1, b3, acc[1][3]);
        acc[2][0] = fmaf(a2, b0, acc[2][0]); acc[2][1] = fmaf(a2, b1, acc[2][1]);
        acc[2][2] = fmaf(a2, b2, acc[2][2]); acc[2][3] = fmaf(a2, b3, acc[2][3]);
        acc[3][0] = fmaf(a3, b0, acc[3][0]); acc[3][1] = fmaf(a3, b1, acc[3][1]);
        acc[3][2] = fmaf(a3, b2, acc[3][2]); acc[3][3] = fmaf(a3, b3, acc[3][3]);
    }
#pragma unroll
    for (int i = 0; i < 4; i++)
#pragma unroll
        for (int j = 0; j < 4; j++)
            g_proj[(n0 + ti * 4 + i) * 256 + h * 64 + tc * 4 + j] = acc[i][j];
}

// =====================================================================
// K1b: skip GEMM g_skip = nodes @ skw^T. grid (64,4).
// =====================================================================
__global__ void __launch_bounds__(256) k_skip(
    const float* __restrict__ nodes, const float* __restrict__ skw) {
    __shared__ float x_s[64][129];
    __shared__ float w_s[64][129];
    int tid = threadIdx.x;
    int n0 = blockIdx.x * 64, c0 = blockIdx.y * 64;
#pragma unroll
    for (int it = 0; it < 32; it++) {
        int idx = it * 256 + tid;
        int r = idx >> 7, f = idx & 127;
        x_s[r][f] = nodes[(n0 + r) * 128 + f];
        w_s[r][f] = skw[(c0 + r) * 128 + f];
    }
    __syncthreads();
    int ti = tid >> 4, tc = tid & 15;
    float acc[4][4];
#pragma unroll
    for (int i = 0; i < 4; i++)
#pragma unroll
        for (int j = 0; j < 4; j++) acc[i][j] = 0.f;
#pragma unroll 4
    for (int k = 0; k < 128; k++) {
        float a0 = x_s[ti * 4 + 0][k], a1 = x_s[ti * 4 + 1][k];
        float a2 = x_s[ti * 4 + 2][k], a3 = x_s[ti * 4 + 3][k];
        float b0 = w_s[tc * 4 + 0][k], b1 = w_s[tc * 4 + 1][k];
        float b2 = w_s[tc * 4 + 2][k], b3 = w_s[tc * 4 + 3][k];
        acc[0][0] = fmaf(a0, b0, acc[0][0]); acc[0][1] = fmaf(a0, b1, acc[0][1]);
        acc[0][2] = fmaf(a0, b2, acc[0][2]); acc[0][3] = fmaf(a0, b3, acc[0][3]);
        acc[1][0] = fmaf(a1, b0, acc[1][0]); acc[1][1] = fmaf(a1, b1, acc[1][1]);
        acc[1][2] = fmaf(a1, b2, acc[1][2]); acc[1][3] = fmaf(a1, b3, acc[1][3]);
        acc[2][0] = fmaf(a2, b0, acc[2][0]); acc[2][1] = fmaf(a2, b1, acc[2][1]);
        acc[2][2] = fmaf(a2, b2, acc[2][2]); acc[2][3] = fmaf(a2, b3, acc[2][3]);
        acc[3][0] = fmaf(a3, b0, acc[3][0]); acc[3][1] = fmaf(a3, b1, acc[3][1]);
        acc[3][2] = fmaf(a3, b2, acc[3][2]); acc[3][3] = fmaf(a3, b3, acc[3][3]);
    }
#pragma unroll
    for (int i = 0; i < 4; i++)
#pragma unroll
        for (int j = 0; j < 4; j++)
            g_skip[(n0 + ti * 4 + i) * 256 + c0 + tc * 4 + j] = acc[i][j];
}

// =====================================================================
// K1c: scalar scores via warp dot. grid 2048, 256 threads.
// =====================================================================
__global__ void __launch_bounds__(256) k_score(
    const float* __restrict__ scs, const float* __restrict__ sct) {
    int w = threadIdx.x >> 5, l = threadIdx.x & 31;
    int hn = blockIdx.x * 8 + w;
    int h = hn >> 12, n = hn & 4095;
    float p0 = g_proj[n * 256 + h * 64 + l];
    float p1 = g_proj[n * 256 + h * 64 + 32 + l];
    float vs = p0 * scs[h * 64 + l] + p1 * scs[h * 64 + 32 + l];
    float vt = p0 * sct[h * 64 + l] + p1 * sct[h * 64 + 32 + l];
#pragma unroll
    for (int s = 16; s > 0; s >>= 1) {
        vs += __shfl_xor_sync(0xffffffffu, vs, s);
        vt += __shfl_xor_sync(0xffffffffu, vt, s);
    }
    if (l == 0) {
        g_ss[h * 4096 + n] = vs;
        g_st[h * 4096 + n] = vt;
    }
}

// =====================================================================
// K2: mask build + per-row LayerNorm, float4. grid 4096, 256 threads.
// =====================================================================
__global__ void __launch_bounds__(256) k_mask(
    const float4* __restrict__ deg4, const float4* __restrict__ bond4,
    const int* __restrict__ cutp, float4* __restrict__ out_ln4) {
    __shared__ float red[256];
    int i = blockIdx.x, tid = threadIdx.x;
    float cut = (float)cutp[0];
    float4* gm4 = reinterpret_cast<float4*>(g_mask);
    float4 mv[4];
    float ssum = 0.f;
#pragma unroll
    for (int k = 0; k < 4; k++) {
        int idx = i * 1024 + tid + k * 256;
        float4 d = deg4[idx], b = bond4[idx];
        float4 m;
        {
            float w0 = d.x + b.x; m.x = (w0 > 0.f) ? w0 : ((b.x > cut) ? (b.x + w0) : NEG_INF);
            float w1 = d.y + b.y; m.y = (w1 > 0.f) ? w1 : ((b.y > cut) ? (b.y + w1) : NEG_INF);
            float w2 = d.z + b.z; m.z = (w2 > 0.f) ? w2 : ((b.z > cut) ? (b.z + w2) : NEG_INF);
            float w3 = d.w + b.w; m.w = (w3 > 0.f) ? w3 : ((b.w > cut) ? (b.w + w3) : NEG_INF);
        }
        mv[k] = m;
        gm4[idx] = m;
        ssum += m.x + m.y + m.z + m.w;
    }
    float mu = bred256(ssum, red, tid) * (1.f / 4096.f);
    float s2 = 0.f;
#pragma unroll
    for (int k = 0; k < 4; k++) {
        float dx = mv[k].x - mu, dy = mv[k].y - mu, dz = mv[k].z - mu, dw = mv[k].w - mu;
        s2 = fmaf(dx, dx, s2); s2 = fmaf(dy, dy, s2);
        s2 = fmaf(dz, dz, s2); s2 = fmaf(dw, dw, s2);
    }
    float var = bred256(s2, red, tid) * (1.f / 4096.f);
    float rstd = rsqrtf(var + 1e-5f);
#pragma unroll
    for (int k = 0; k < 4; k++) {
        int idx = i * 1024 + tid + k * 256;
        float4 o;
        o.x = (mv[k].x - mu) * rstd; o.y = (mv[k].y - mu) * rstd;
        o.z = (mv[k].z - mu) * rstd; o.w = (mv[k].w - mu) * rstd;
        out_ln4[idx] = o;
    }
}

// =====================================================================
// K3: partial column softmax stats, 8-elem chunks. grid (32,8,4), 128 thr.
// =====================================================================
__global__ void __launch_bounds__(128) k_stats() {
    __shared__ float ss_s[512];
    int tid = threadIdx.x;
    int jc = blockIdx.x, istr = blockIdx.y, h = blockIdx.z;
    int j = jc * 128 + tid;
    int i0 = istr * 512;
#pragma unroll
    for (int k = 0; k < 4; k++) ss_s[tid + k * 128] = g_ss[h * 4096 + i0 + tid + k * 128];
    __syncthreads();
    float stj = g_st[h * 4096 + j];
    float m = -INFINITY, z = 0.f;
    for (int c = 0; c < 512; c += 8) {
        float mkv[8];
#pragma unroll
        for (int k = 0; k < 8; k++)
            mkv[k] = g_mask[(unsigned)(i0 + c + k) * 4096u + (unsigned)j];
        float e[8];
#pragma unroll
        for (int k = 0; k < 8; k++) {
            float t = ss_s[c + k] + stj;
            t = fmaxf(t, 0.2f * t);
            e[k] = t + mkv[k];
        }
        float cm = fmaxf(fmaxf(fmaxf(e[0], e[1]), fmaxf(e[2], e[3])),
                         fmaxf(fmaxf(e[4], e[5]), fmaxf(e[6], e[7])));
        float nm = fmaxf(m, cm);
        float cz = 0.f;
#pragma unroll
        for (int k = 0; k < 8; k++) cz += __expf(e[k] - nm);
        z = fmaf(z, __expf(m - nm), cz);
        m = nm;
    }
    g_pm[(h * 8 + istr) * 4096 + j] = m;
    g_pz[(h * 8 + istr) * 4096 + j] = z;
}

// =====================================================================
// K4: combine stripe partials. grid 64, 256 threads.
// =====================================================================
__global__ void __launch_bounds__(256) k_comb() {
    int idx = blockIdx.x * 256 + threadIdx.x;
    int h = idx >> 12, j = idx & 4095;
    float m = -INFINITY;
#pragma unroll
    for (int s = 0; s < 8; s++) m = fmaxf(m, g_pm[(h * 8 + s) * 4096 + j]);
    float z = 0.f;
#pragma unroll
    for (int s = 0; s < 8; s++)
        z += g_pz[(h * 8 + s) * 4096 + j] * __expf(g_pm[(h * 8 + s) * 4096 + j] - m);
    g_m[h * 4096 + j] = m;
    g_iz[h * 4096 + j] = 1.0f / z;
}

// =====================================================================
// K5 v3: aggregation + skip + ELU, double-buffered, SMALL tile.
// grid (64 i-blocks of 64 rows, 4 heads), 256 threads, 2 CTAs/SM pinned.
// Thread tile 4 rows x 8 f => acc[4][4] u64 = 32 regs (R10's 64-reg acc
// caused spills / 1 CTA/SM and the regression).
// =====================================================================
__global__ void __launch_bounds__(256, 2) k_agg(float* __restrict__ out) {
    __shared__ __align__(16) float w_s[2][64][33];
    __shared__ __align__(16) float proj_s[2][32][68];
    __shared__ float ss_s[64];

    int tid = threadIdx.x;
    int h = blockIdx.y;
    int i0 = blockIdx.x * 64;
    if (tid < 64) ss_s[tid] = g_ss[h * 4096 + i0 + tid];

    int jhalf = tid >> 7;        // 0/1: j sub-range this thread accumulates
    int ct = tid & 127;
    int i_g = ct >> 3;           // 0..15 -> rows i_g*4 .. +3
    int f_g = ct & 7;            // cols f_g*4..+3 and 32+f_g*4..+3
    int jw = tid & 31;           // w-phase column lane
    int iw = tid >> 3 & 0;       // (unused placeholder)
    int iwr = tid >> 5;          // w-phase row offset 0..7
    int jlo = jhalf * 16;

    unsigned long long acc[4][4];
#pragma unroll
    for (int r = 0; r < 4; r++)
#pragma unroll
        for (int q = 0; q < 4; q++) acc[r][q] = 0ull;

    __syncthreads();  // ss_s ready

    // ---- prologue: fill buffer 0 (tile j0 = 0) ----
    {
        float stj = g_st[h * 4096 + jw];
        float mj = g_m[h * 4096 + jw];
        float izj = g_iz[h * 4096 + jw];
        float pv[8];
#pragma unroll
        for (int p = 0; p < 8; p++) {
            int idx = p * 256 + tid;  // 2048 = 32j x 64f
            pv[p] = g_proj[(idx >> 6) * 256 + h * 64 + (idx & 63)];
        }
#pragma unroll
        for (int p = 0; p < 8; p++) {
            int il = p * 8 + iwr;
            float e = ss_s[il] + stj;
            e = fmaxf(e, 0.2f * e);
            e += g_mask[(unsigned)(i0 + il) * 4096u + (unsigned)jw];
            w_s[0][il][jw] = __expf(e - mj) * izj;
        }
#pragma unroll
        for (int p = 0; p < 8; p++) {
            int idx = p * 256 + tid;
            proj_s[0][idx >> 6][idx & 63] = pv[p];
        }
    }
    __syncthreads();

    for (int t = 0; t < 128; t++) {
        int cur = t & 1, nxt = cur ^ 1;
        int nj0 = (t + 1) * 32;
        bool pf = (t + 1) < 128;

        float stj = 0.f, mj = 0.f, izj = 1.f;
        float mk[8], pv[8];
        if (pf) {
            stj = g_st[h * 4096 + nj0 + jw];
            mj = g_m[h * 4096 + nj0 + jw];
            izj = g_iz[h * 4096 + nj0 + jw];
#pragma unroll
            for (int p = 0; p < 8; p++) {
                int idx = p * 256 + tid;
                pv[p] = g_proj[(nj0 + (idx >> 6)) * 256 + h * 64 + (idx & 63)];
            }
#pragma unroll
            for (int p = 0; p < 8; p++) {
                int il = p * 8 + iwr;
                mk[p] = g_mask[(unsigned)(i0 + il) * 4096u + (unsigned)(nj0 + jw)];
            }
        }

        // ---- FMA on current buffer ----
#pragma unroll
        for (int jj = 0; jj < 16; jj++) {
            int jl = jlo + jj;
            ulonglong2 pA = *(const ulonglong2*)&proj_s[cur][jl][f_g * 4];
            ulonglong2 pB = *(const ulonglong2*)&proj_s[cur][jl][32 + f_g * 4];
            float w0 = w_s[cur][i_g * 4 + 0][jl];
            float w1 = w_s[cur][i_g * 4 + 1][jl];
            float w2 = w_s[cur][i_g * 4 + 2][jl];
            float w3 = w_s[cur][i_g * 4 + 3][jl];
            unsigned long long u0 = pk2(w0, w0), u1 = pk2(w1, w1);
            unsigned long long u2 = pk2(w2, w2), u3 = pk2(w3, w3);
            acc[0][0] = fma2_(u0, pA.x, acc[0][0]); acc[0][1] = fma2_(u0, pA.y, acc[0][1]);
            acc[0][2] = fma2_(u0, pB.x, acc[0][2]); acc[0][3] = fma2_(u0, pB.y, acc[0][3]);
            acc[1][0] = fma2_(u1, pA.x, acc[1][0]); acc[1][1] = fma2_(u1, pA.y, acc[1][1]);
            acc[1][2] = fma2_(u1, pB.x, acc[1][2]); acc[1][3] = fma2_(u1, pB.y, acc[1][3]);
            acc[2][0] = fma2_(u2, pA.x, acc[2][0]); acc[2][1] = fma2_(u2, pA.y, acc[2][1]);
            acc[2][2] = fma2_(u2, pB.x, acc[2][2]); acc[2][3] = fma2_(u2, pB.y, acc[2][3]);
            acc[3][0] = fma2_(u3, pA.x, acc[3][0]); acc[3][1] = fma2_(u3, pA.y, acc[3][1]);
            acc[3][2] = fma2_(u3, pB.x, acc[3][2]); acc[3][3] = fma2_(u3, pB.y, acc[3][3]);
        }

        // ---- write next buffer ----
        if (pf) {
#pragma unroll
            for (int p = 0; p < 8; p++) {
                int il = p * 8 + iwr;
                float e = ss_s[il] + stj;
                e = fmaxf(e, 0.2f * e);
                e += mk[p];
                w_s[nxt][il][jw] = __expf(e - mj) * izj;
            }
#pragma unroll
            for (int p = 0; p < 8; p++) {
                int idx = p * 256 + tid;
                proj_s[nxt][idx >> 6][idx & 63] = pv[p];
            }
        }
        __syncthreads();
    }

    // ---- pair-reduce the two j-halves through smem, skip+ELU epilogue ----
    unsigned long long* red = reinterpret_cast<unsigned long long*>(&w_s[0][0][0]);
    if (jhalf == 1) {
#pragma unroll
        for (int r = 0; r < 4; r++)
#pragma unroll
            for (int q = 0; q < 4; q++) red[ct * 16 + r * 4 + q] = acc[r][q];
    }
    __syncthreads();
    if (jhalf == 0) {
#pragma unroll
        for (int r = 0; r < 4; r++) {
            int n = i0 + i_g * 4 + r;
#pragma unroll
            for (int q = 0; q < 4; q++) {
                float x0, x1, y0, y1;
                upk2(acc[r][q], x0, x1);
                upk2(red[ct * 16 + r * 4 + q], y0, y1);
                x0 += y0; x1 += y1;
                int cb = (q < 2) ? (f_g * 4 + q * 2) : (32 + f_g * 4 + (q - 2) * 2);
                int c = h * 64 + cb;
                float v0 = x0 + g_skip[n * 256 + c];
                float v1 = x1 + g_skip[n * 256 + c + 1];
                out[n * 256 + c] = (v0 > 0.f) ? v0 : expm1f(v0);
                out[n * 256 + c + 1] = (v1 > 0.f) ? v1 : expm1f(v1);
            }
        }
    }
}

// =====================================================================
extern "C" void kernel_launch(void* const* d_in, const int* in_sizes, int n_in,
                              void* d_out, int out_size) {
    const float* nodes = (const float*)d_in[0];
    const float* deg = (const float*)d_in[1];
    const float* bond = (const float*)d_in[3];
    const float* pp = (const float*)d_in[4];
    const float* scs = (const float*)d_in[5];
    const float* sct = (const float*)d_in[6];
    const float* skw = (const float*)d_in[7];
    const int* cutp = (const int*)d_in[8];

    float* out0 = (float*)d_out;        // [4096,256]
    float* out_ln = out0 + 4096 * 256;  // [4096,4096]

    k_projg<<<dim3(64, 4), 256>>>(nodes, pp);
    k_skip<<<dim3(64, 4), 256>>>(nodes, skw);
    k_score<<<2048, 256>>>(scs, sct);
    k_mask<<<4096, 256>>>((const float4*)deg, (const float4*)bond, cutp,
                          (float4*)out_ln);
    k_stats<<<dim3(32, 8, 4), 128>>>();
    k_comb<<<64, 256>>>();
    k_agg<<<dim3(64, 4), 256>>>(out0);
}